// round 1
// baseline (speedup 1.0000x reference)
#include <cuda_runtime.h>

// ---------------------------------------------------------------------------
// HybridQLSTM:
//   K1: Xpre[t][g][w] = emb[sent[t]] . Wg[w, :1024] + b[w] + theta[w]   (parallel)
//   K2: serial scan over T steps, one warp, lanes = (gate g, wire w).
//       qlayer reduced analytically to products of cos(pre).
//   K3: tag logits + log_softmax                                         (parallel)
// ---------------------------------------------------------------------------

#define T_MAX 8192

__device__ float g_Xpre[T_MAX * 16];   // [t][gate][wire], bias+theta folded in
__device__ float g_hout[T_MAX * 4];    // h_t per step

__device__ __forceinline__ float sigm_(float x) {
    return 1.0f / (1.0f + __expf(-x));
}
__device__ __forceinline__ float tanh_(float x) {
    // 2*sigmoid(2x) - 1, via fast exp (rel err ~2^-20, fine for 1e-3 gate)
    return 2.0f / (1.0f + __expf(-2.0f * x)) - 1.0f;
}

// ---------------------------------------------------------------------------
// K1: per-step input pre-activations. Persistent blocks; each of 16 warps owns
// one (gate, wire) weight row held in registers; embedding rows streamed.
// ---------------------------------------------------------------------------
__global__ void k1_pre(const int* __restrict__ sent,
                       const float* __restrict__ emb,
                       const float* __restrict__ Wf, const float* __restrict__ bf,
                       const float* __restrict__ Wi, const float* __restrict__ bi,
                       const float* __restrict__ Wu, const float* __restrict__ bu,
                       const float* __restrict__ Wo, const float* __restrict__ bo,
                       const float* __restrict__ thf, const float* __restrict__ thi,
                       const float* __restrict__ thu, const float* __restrict__ tho,
                       int T)
{
    const int warp = threadIdx.x >> 5;
    const int lane = threadIdx.x & 31;
    const int g = warp >> 2, w = warp & 3;

    const float* Wg = (g == 0) ? Wf : (g == 1) ? Wi : (g == 2) ? Wu : Wo;
    const float* bg = (g == 0) ? bf : (g == 1) ? bi : (g == 2) ? bu : bo;
    const float* tg = (g == 0) ? thf : (g == 1) ? thi : (g == 2) ? thu : tho;

    const float bias = bg[w] + tg[w];

    // Weight row (1024 floats) cached in 32 registers per lane.
    const float4* w4 = (const float4*)(Wg + (size_t)w * 1028);
    float4 wr[8];
#pragma unroll
    for (int i = 0; i < 8; i++) wr[i] = w4[lane + 32 * i];

    for (int t = blockIdx.x; t < T; t += gridDim.x) {
        const int row = sent[t];
        const float4* e4 = (const float4*)(emb + (size_t)row * 1024);
        float acc = 0.0f;
#pragma unroll
        for (int i = 0; i < 8; i++) {
            float4 a = __ldg(&e4[lane + 32 * i]);
            acc = fmaf(a.x, wr[i].x, acc);
            acc = fmaf(a.y, wr[i].y, acc);
            acc = fmaf(a.z, wr[i].z, acc);
            acc = fmaf(a.w, wr[i].w, acc);
        }
#pragma unroll
        for (int s = 16; s > 0; s >>= 1)
            acc += __shfl_xor_sync(0xffffffffu, acc, s);
        if (lane == 0) g_Xpre[t * 16 + warp] = acc + bias;
    }
}

// ---------------------------------------------------------------------------
// K2: serial LSTM scan, one warp. Lane li = g*4 + w (mirrored in upper half).
// qlayer(a)[w] = product of cos over the wire subset:
//   w=0: c1*c2*c3   w=1: c0*c1   w=2: c0*c1*c2   w=3: c0*c1*c2*c3
// ---------------------------------------------------------------------------
__global__ void k2_scan(const float* __restrict__ Wf, const float* __restrict__ Wi,
                        const float* __restrict__ Wu, const float* __restrict__ Wo,
                        int T)
{
    const unsigned FULL = 0xffffffffu;
    const int lane = threadIdx.x;
    const int li = lane & 15;
    const int g = li >> 2, w = li & 3;
    const int base = li & ~3;

    const float* Wg = (g == 0) ? Wf : (g == 1) ? Wi : (g == 2) ? Wu : Wo;
    const float wh0 = Wg[w * 1028 + 1024];
    const float wh1 = Wg[w * 1028 + 1025];
    const float wh2 = Wg[w * 1028 + 1026];
    const float wh3 = Wg[w * 1028 + 1027];

    float h = 0.0f, c = 0.0f;

    // two-deep prefetch pipeline for Xpre (L2-resident after K1)
    float x0 = g_Xpre[li];
    float x1 = (T > 1) ? g_Xpre[16 + li] : 0.0f;

    for (int t = 0; t < T; t++) {
        const float x = x0;
        x0 = x1;
        x1 = (t + 2 < T) ? g_Xpre[(t + 2) * 16 + li] : 0.0f;

        // broadcast previous h within gate group
        const float h0 = __shfl_sync(FULL, h, base + 0);
        const float h1 = __shfl_sync(FULL, h, base + 1);
        const float h2 = __shfl_sync(FULL, h, base + 2);
        const float h3 = __shfl_sync(FULL, h, base + 3);

        float pre = x;
        pre = fmaf(h0, wh0, pre);
        pre = fmaf(h1, wh1, pre);
        pre = fmaf(h2, wh2, pre);
        pre = fmaf(h3, wh3, pre);

        const float cs = __cosf(pre);

        const float c0 = __shfl_sync(FULL, cs, base + 0);
        const float c1 = __shfl_sync(FULL, cs, base + 1);
        const float c2 = __shfl_sync(FULL, cs, base + 2);
        const float c3 = __shfl_sync(FULL, cs, base + 3);

        const float t01 = c0 * c1;
        const float t012 = t01 * c2;
        const float z = (w == 0) ? c1 * c2 * c3
                      : (w == 1) ? t01
                      : (w == 2) ? t012
                                 : t012 * c3;

        const float gv = (g == 2) ? tanh_(z) : sigm_(z);

        // gather f, i, u, o for this lane's wire
        const float fv = __shfl_sync(FULL, gv, 0 + w);
        const float iv = __shfl_sync(FULL, gv, 4 + w);
        const float uv = __shfl_sync(FULL, gv, 8 + w);
        const float ov = __shfl_sync(FULL, gv, 12 + w);

        c = fmaf(fv, c, iv * uv);
        h = ov * tanh_(c);

        if (lane < 4) g_hout[t * 4 + w] = h;
    }
}

// ---------------------------------------------------------------------------
// K3: tag logits + log_softmax. One warp per timestep; lane covers up to
// two tags (TAG = 50).
// ---------------------------------------------------------------------------
__global__ void k3_tag(const float* __restrict__ Wt, const float* __restrict__ bt,
                       float* __restrict__ out, int T, int TAG)
{
    const int warp_global = (int)((blockIdx.x * blockDim.x + threadIdx.x) >> 5);
    const int lane = threadIdx.x & 31;
    if (warp_global >= T) return;
    const int t = warp_global;

    const float h0 = g_hout[t * 4 + 0];
    const float h1 = g_hout[t * 4 + 1];
    const float h2 = g_hout[t * 4 + 2];
    const float h3 = g_hout[t * 4 + 3];

    const int tag0 = lane;
    const int tag1 = lane + 32;

    float l0 = -1e30f, l1 = -1e30f;
    if (tag0 < TAG) {
        const float* wr = Wt + tag0 * 4;
        l0 = bt[tag0] + h0 * wr[0] + h1 * wr[1] + h2 * wr[2] + h3 * wr[3];
    }
    if (tag1 < TAG) {
        const float* wr = Wt + tag1 * 4;
        l1 = bt[tag1] + h0 * wr[0] + h1 * wr[1] + h2 * wr[2] + h3 * wr[3];
    }

    float m = fmaxf(l0, l1);
#pragma unroll
    for (int s = 16; s > 0; s >>= 1)
        m = fmaxf(m, __shfl_xor_sync(0xffffffffu, m, s));

    float s0 = (tag0 < TAG) ? __expf(l0 - m) : 0.0f;
    float s1 = (tag1 < TAG) ? __expf(l1 - m) : 0.0f;
    float ssum = s0 + s1;
#pragma unroll
    for (int s = 16; s > 0; s >>= 1)
        ssum += __shfl_xor_sync(0xffffffffu, ssum, s);

    const float lse = m + __logf(ssum);
    if (tag0 < TAG) out[t * TAG + tag0] = l0 - lse;
    if (tag1 < TAG) out[t * TAG + tag1] = l1 - lse;
}

// ---------------------------------------------------------------------------
extern "C" void kernel_launch(void* const* d_in, const int* in_sizes, int n_in,
                              void* d_out, int out_size)
{
    const int*   sent = (const int*)  d_in[0];
    const float* emb  = (const float*)d_in[1];
    const float* Wf   = (const float*)d_in[2];
    const float* bf   = (const float*)d_in[3];
    const float* Wi   = (const float*)d_in[4];
    const float* bi   = (const float*)d_in[5];
    const float* Wu   = (const float*)d_in[6];
    const float* bu   = (const float*)d_in[7];
    const float* Wo   = (const float*)d_in[8];
    const float* bo   = (const float*)d_in[9];
    const float* thf  = (const float*)d_in[10];
    const float* thi  = (const float*)d_in[11];
    const float* thu  = (const float*)d_in[12];
    const float* tho  = (const float*)d_in[13];
    const float* Wt   = (const float*)d_in[14];
    const float* bt   = (const float*)d_in[15];

    int T = in_sizes[0];
    if (T > T_MAX) T = T_MAX;
    const int TAG = in_sizes[14] / 4;   // Wt is [TAG, 4]

    k1_pre<<<256, 512>>>(sent, emb, Wf, bf, Wi, bi, Wu, bu, Wo, bo,
                         thf, thi, thu, tho, T);
    k2_scan<<<1, 32>>>(Wf, Wi, Wu, Wo, T);

    const int warps_per_block = 8;
    const int blocks = (T + warps_per_block - 1) / warps_per_block;
    k3_tag<<<blocks, warps_per_block * 32>>>(Wt, bt, (float*)d_out, T, TAG);
}

// round 4
// speedup vs baseline: 2.0091x; 2.0091x over previous
#include <cuda_runtime.h>

// ---------------------------------------------------------------------------
// HybridQLSTM:
//   K1: XpreT[g*4+w][t] = emb[sent[t]] . Wg[w,:1024] + b[w] + theta[w]  (parallel)
//   K2: serial scan, one warp, lanes = (gate g, wire w); qlayer reduced to
//       products of cos; all activations via one rational tanh (no exp).
//       Transposed Xpre + float4 prefetch; manual unroll-4.
//   K3: tag logits + log_softmax                                        (parallel)
// ---------------------------------------------------------------------------

#define T_MAX 8192
#define T_PAD (T_MAX + 16)

__device__ __align__(16) float g_XpreT[16 * T_PAD];  // [lane li][t]; zero-init tail
__device__ __align__(16) float g_houtT[4 * T_PAD];   // [wire][t]

// rational tanh: x*(945 + 105 x^2 + x^4) / (945 + 420 x^2 + 15 x^4)
// err <= 5e-8 on |x|<=1, <= 4e-5 on |x|<=2.1  (|c| provably <= 2.071)
__device__ __forceinline__ float tanh_rat(float x) {
    const float x2 = x * x;
    const float p  = x2 + 105.0f;
    const float q  = fmaf(x2, p, 945.0f);
    const float nm = x * q;
    const float r  = fmaf(x2, 15.0f, 420.0f);
    const float dn = fmaf(x2, r, 945.0f);
    return __fdividef(nm, dn);          // MUFU.RCP + FMUL
}

// ---------------------------------------------------------------------------
// K1: per-step input pre-activations. 16 warps/block, each owns one (gate,wire)
// weight row in registers; two timesteps in flight per block for MLP.
// ---------------------------------------------------------------------------
__global__ void k1_pre(const int* __restrict__ sent,
                       const float* __restrict__ emb,
                       const float* __restrict__ Wf, const float* __restrict__ bf,
                       const float* __restrict__ Wi, const float* __restrict__ bi,
                       const float* __restrict__ Wu, const float* __restrict__ bu,
                       const float* __restrict__ Wo, const float* __restrict__ bo,
                       const float* __restrict__ thf, const float* __restrict__ thi,
                       const float* __restrict__ thu, const float* __restrict__ tho,
                       int T)
{
    const int warp = threadIdx.x >> 5;
    const int lane = threadIdx.x & 31;
    const int g = warp >> 2, w = warp & 3;

    const float* Wg = (g == 0) ? Wf : (g == 1) ? Wi : (g == 2) ? Wu : Wo;
    const float* bg = (g == 0) ? bf : (g == 1) ? bi : (g == 2) ? bu : bo;
    const float* tg = (g == 0) ? thf : (g == 1) ? thi : (g == 2) ? thu : tho;

    const float bias = bg[w] + tg[w];

    // Weight row (1024 floats) cached in 32 registers per lane.
    const float4* w4 = (const float4*)(Wg + (size_t)w * 1028);
    float4 wr[8];
#pragma unroll
    for (int i = 0; i < 8; i++) wr[i] = w4[lane + 32 * i];

    float* xrow = &g_XpreT[warp * T_PAD];

    const int stride = gridDim.x;
    for (int t = blockIdx.x; t < T; t += 2 * stride) {
        const int t2 = t + stride;
        const bool has2 = (t2 < T);

        const int row1 = sent[t];
        const int row2 = has2 ? sent[t2] : row1;
        const float4* e1 = (const float4*)(emb + (size_t)row1 * 1024);
        const float4* e2 = (const float4*)(emb + (size_t)row2 * 1024);

        float acc1 = 0.0f, acc2 = 0.0f;
#pragma unroll
        for (int i = 0; i < 8; i++) {
            float4 a = __ldg(&e1[lane + 32 * i]);
            float4 b = __ldg(&e2[lane + 32 * i]);
            acc1 = fmaf(a.x, wr[i].x, acc1);
            acc1 = fmaf(a.y, wr[i].y, acc1);
            acc1 = fmaf(a.z, wr[i].z, acc1);
            acc1 = fmaf(a.w, wr[i].w, acc1);
            acc2 = fmaf(b.x, wr[i].x, acc2);
            acc2 = fmaf(b.y, wr[i].y, acc2);
            acc2 = fmaf(b.z, wr[i].z, acc2);
            acc2 = fmaf(b.w, wr[i].w, acc2);
        }
#pragma unroll
        for (int s = 16; s > 0; s >>= 1) {
            acc1 += __shfl_xor_sync(0xffffffffu, acc1, s);
            acc2 += __shfl_xor_sync(0xffffffffu, acc2, s);
        }
        if (lane == 0) {
            xrow[t] = acc1 + bias;
            if (has2) xrow[t2] = acc2 + bias;
        }
    }
}

// ---------------------------------------------------------------------------
// K2: serial LSTM scan, one warp. Lane li = g*4 + w (mirrored in upper half).
// qlayer(a)[w]: w=0: c1c2c3  w=1: c0c1  w=2: c0c1c2  w=3: c0c1c2c3
// ---------------------------------------------------------------------------
struct K2Consts {
    float wr0, wr1, wr2, wr3;
    int hs1, hs2, hs3;
    int sA, sB, sC;
    float f0_ident, fB_ident, fC_ident;   // 1 if identity else 0 (select flags as float? use bool)
    bool wz0, wB1, wC12;
    float act_s, act_a, act_b;
    int w;
};

__device__ __forceinline__ void lstm_step(float x, float& h, float& c,
                                          const K2Consts& K)
{
    const unsigned FULL = 0xffffffffu;

    // h broadcast (3 shuffles; own h in-lane)
    const float h1 = __shfl_sync(FULL, h, K.hs1);
    const float h2 = __shfl_sync(FULL, h, K.hs2);
    const float h3 = __shfl_sync(FULL, h, K.hs3);

    // pre-activation, depth-3 FMA tree
    const float pa = fmaf(h, K.wr0, x);
    const float pb = h1 * K.wr1;
    const float pc = fmaf(h2, K.wr2, pb);
    const float pd = fmaf(h3, K.wr3, pa);
    const float pre = pc + pd;

    const float cs = __cosf(pre);

    // z = product of required cosines (3 shuffles + identity selects)
    const float fA  = __shfl_sync(FULL, cs, K.sA);
    const float fBs = __shfl_sync(FULL, cs, K.sB);
    const float fCs = __shfl_sync(FULL, cs, K.sC);
    const float f0 = K.wz0  ? 1.0f : cs;
    const float fB = K.wB1  ? 1.0f : fBs;
    const float fC = K.wC12 ? 1.0f : fCs;
    const float z  = (f0 * fA) * (fB * fC);

    // activation: sigmoid = 0.5 + 0.5*tanh(z/2); u-gate = tanh(z)
    const float gv = fmaf(tanh_rat(K.act_s * z), K.act_a, K.act_b);

    // gather f, i, u, o at this lane's wire
    const float fv = __shfl_sync(FULL, gv, 0 + K.w);
    const float iv = __shfl_sync(FULL, gv, 4 + K.w);
    const float uv = __shfl_sync(FULL, gv, 8 + K.w);
    const float ov = __shfl_sync(FULL, gv, 12 + K.w);

    c = fmaf(fv, c, iv * uv);
    h = ov * tanh_rat(c);
}

__global__ void k2_scan(const float* __restrict__ Wf, const float* __restrict__ Wi,
                        const float* __restrict__ Wu, const float* __restrict__ Wo,
                        int T)
{
    const int lane = threadIdx.x;
    const int li = lane & 15;
    const int g = li >> 2, w = li & 3;
    const int base = li & ~3;

    const float* Wg = (g == 0) ? Wf : (g == 1) ? Wi : (g == 2) ? Wu : Wo;

    K2Consts K;
    // rotated recurrent weights: wr_k multiplies h[(w+k)&3]; own h needs no shuffle
    K.wr0 = Wg[w * 1028 + 1024 + w];
    K.wr1 = Wg[w * 1028 + 1024 + ((w + 1) & 3)];
    K.wr2 = Wg[w * 1028 + 1024 + ((w + 2) & 3)];
    K.wr3 = Wg[w * 1028 + 1024 + ((w + 3) & 3)];
    K.hs1 = base + ((w + 1) & 3);
    K.hs2 = base + ((w + 2) & 3);
    K.hs3 = base + ((w + 3) & 3);
    K.sA = base + ((w == 0) ? 1 : 0);
    K.sB = base + ((w >= 2) ? 1 : ((w == 0) ? 2 : 0));
    K.sC = base + ((w == 0) ? 3 : ((w == 3) ? 2 : 0));
    K.wz0  = (w == 0);
    K.wB1  = (w == 1);
    K.wC12 = (w == 1) || (w == 2);
    K.act_s = (g == 2) ? 1.0f : 0.5f;
    K.act_a = (g == 2) ? 1.0f : 0.5f;
    K.act_b = (g == 2) ? 0.0f : 0.5f;
    K.w = w;

    const float* xrow = &g_XpreT[li * T_PAD];
    float* hrow = &g_houtT[w * T_PAD];
    const bool do_store = (lane < 4);

    float h = 0.0f, c = 0.0f;

    const int Tr = (T + 3) & ~3;   // T=8192 -> 8192

    // double-buffered float4 prefetch; tail of xrow is zero-padded
    float4 cur = *(const float4*)&xrow[0];
    float4 nxt = *(const float4*)&xrow[4];

    for (int t = 0; t < Tr; t += 4) {
        const float4 use = cur;
        cur = nxt;
        nxt = *(const float4*)&xrow[t + 8];   // max index Tr+11 < T_PAD

        lstm_step(use.x, h, c, K);
        const float hA = h;
        lstm_step(use.y, h, c, K);
        const float hB = h;
        lstm_step(use.z, h, c, K);
        const float hC = h;
        lstm_step(use.w, h, c, K);
        const float hD = h;

        if (do_store)
            *(float4*)&hrow[t] = make_float4(hA, hB, hC, hD);
    }
}

// ---------------------------------------------------------------------------
// K3: tag logits + log_softmax. One warp per timestep; lane covers two tags.
// ---------------------------------------------------------------------------
__global__ void k3_tag(const float* __restrict__ Wt, const float* __restrict__ bt,
                       float* __restrict__ out, int T, int TAG)
{
    const int warp_global = (int)((blockIdx.x * blockDim.x + threadIdx.x) >> 5);
    const int lane = threadIdx.x & 31;
    if (warp_global >= T) return;
    const int t = warp_global;

    const float h0 = g_houtT[0 * T_PAD + t];
    const float h1 = g_houtT[1 * T_PAD + t];
    const float h2 = g_houtT[2 * T_PAD + t];
    const float h3 = g_houtT[3 * T_PAD + t];

    const int tag0 = lane;
    const int tag1 = lane + 32;

    float l0 = -1e30f, l1 = -1e30f;
    if (tag0 < TAG) {
        const float* wr = Wt + tag0 * 4;
        l0 = bt[tag0] + h0 * wr[0] + h1 * wr[1] + h2 * wr[2] + h3 * wr[3];
    }
    if (tag1 < TAG) {
        const float* wr = Wt + tag1 * 4;
        l1 = bt[tag1] + h0 * wr[0] + h1 * wr[1] + h2 * wr[2] + h3 * wr[3];
    }

    float m = fmaxf(l0, l1);
#pragma unroll
    for (int s = 16; s > 0; s >>= 1)
        m = fmaxf(m, __shfl_xor_sync(0xffffffffu, m, s));

    float s0 = (tag0 < TAG) ? __expf(l0 - m) : 0.0f;
    float s1 = (tag1 < TAG) ? __expf(l1 - m) : 0.0f;
    float ssum = s0 + s1;
#pragma unroll
    for (int s = 16; s > 0; s >>= 1)
        ssum += __shfl_xor_sync(0xffffffffu, ssum, s);

    const float lse = m + __logf(ssum);
    if (tag0 < TAG) out[t * TAG + tag0] = l0 - lse;
    if (tag1 < TAG) out[t * TAG + tag1] = l1 - lse;
}

// ---------------------------------------------------------------------------
extern "C" void kernel_launch(void* const* d_in, const int* in_sizes, int n_in,
                              void* d_out, int out_size)
{
    const int*   sent = (const int*)  d_in[0];
    const float* emb  = (const float*)d_in[1];
    const float* Wf   = (const float*)d_in[2];
    const float* bf   = (const float*)d_in[3];
    const float* Wi   = (const float*)d_in[4];
    const float* bi   = (const float*)d_in[5];
    const float* Wu   = (const float*)d_in[6];
    const float* bu   = (const float*)d_in[7];
    const float* Wo   = (const float*)d_in[8];
    const float* bo   = (const float*)d_in[9];
    const float* thf  = (const float*)d_in[10];
    const float* thi  = (const float*)d_in[11];
    const float* thu  = (const float*)d_in[12];
    const float* tho  = (const float*)d_in[13];
    const float* Wt   = (const float*)d_in[14];
    const float* bt   = (const float*)d_in[15];

    int T = in_sizes[0];
    if (T > T_MAX) T = T_MAX;
    const int TAG = in_sizes[14] / 4;   // Wt is [TAG, 4]

    k1_pre<<<1024, 512>>>(sent, emb, Wf, bf, Wi, bi, Wu, bu, Wo, bo,
                          thf, thi, thu, tho, T);
    k2_scan<<<1, 32>>>(Wf, Wi, Wu, Wo, T);

    const int warps_per_block = 8;
    const int blocks = (T + warps_per_block - 1) / warps_per_block;
    k3_tag<<<blocks, warps_per_block * 32>>>(Wt, bt, (float*)d_out, T, TAG);
}

// round 6
// speedup vs baseline: 45.5840x; 22.6890x over previous
#include <cuda_runtime.h>

// ---------------------------------------------------------------------------
// HybridQLSTM:
//   K1: XpreT[g*4+w][t] = emb[sent[t]] . Wg[w,:1024] + b[w] + theta[w]  (parallel)
//   K2: block-Jacobi parallel scan: 256 blocks of 32 steps; 3 boundary sweeps
//       + 1 output sweep. Contraction (f <= sigma(1)=0.731 => rho_32 ~ 1e-4
//       per sweep) makes the fixed-point iteration converge far below 1e-3.
//   K3: tag logits + log_softmax                                        (parallel)
// ---------------------------------------------------------------------------

#define T_MAX 8192
#define T_PAD (T_MAX + 16)
#define KS 32                    // steps per block
#define NB (T_MAX / KS)          // 256 blocks
#define NSWEEP 3                 // boundary sweeps (then 1 output sweep)

__device__ __align__(16) float g_XpreT[16 * T_PAD];  // [lane li][t]; zero tail
__device__ __align__(16) float g_houtT[4 * T_PAD];   // [wire][t]
__device__ __align__(16) float g_Bh[2][NB][4];       // boundary h (ping-pong)
__device__ __align__(16) float g_Bc[2][NB][4];       // boundary c

// rational tanh: x*(945 + 105 x^2 + x^4) / (945 + 420 x^2 + 15 x^4)
// err <= 5e-8 on |x|<=1, <= 4e-5 on |x|<=2.1  (|c| provably <= 2.071)
__device__ __forceinline__ float tanh_rat(float x) {
    const float x2 = x * x;
    const float p  = x2 + 105.0f;
    const float q  = fmaf(x2, p, 945.0f);
    const float nm = x * q;
    const float r  = fmaf(x2, 15.0f, 420.0f);
    const float dn = fmaf(x2, r, 945.0f);
    return __fdividef(nm, dn);          // MUFU.RCP + FMUL
}

// ---------------------------------------------------------------------------
// K1: per-step input pre-activations (unchanged from passing kernels).
// ---------------------------------------------------------------------------
__global__ void k1_pre(const int* __restrict__ sent,
                       const float* __restrict__ emb,
                       const float* __restrict__ Wf, const float* __restrict__ bf,
                       const float* __restrict__ Wi, const float* __restrict__ bi,
                       const float* __restrict__ Wu, const float* __restrict__ bu,
                       const float* __restrict__ Wo, const float* __restrict__ bo,
                       const float* __restrict__ thf, const float* __restrict__ thi,
                       const float* __restrict__ thu, const float* __restrict__ tho,
                       int T)
{
    const int warp = threadIdx.x >> 5;
    const int lane = threadIdx.x & 31;
    const int g = warp >> 2, w = warp & 3;

    const float* Wg = (g == 0) ? Wf : (g == 1) ? Wi : (g == 2) ? Wu : Wo;
    const float* bg = (g == 0) ? bf : (g == 1) ? bi : (g == 2) ? bu : bo;
    const float* tg = (g == 0) ? thf : (g == 1) ? thi : (g == 2) ? thu : tho;

    const float bias = bg[w] + tg[w];

    const float4* w4 = (const float4*)(Wg + (size_t)w * 1028);
    float4 wr[8];
#pragma unroll
    for (int i = 0; i < 8; i++) wr[i] = w4[lane + 32 * i];

    float* xrow = &g_XpreT[warp * T_PAD];

    const int stride = gridDim.x;
    for (int t = blockIdx.x; t < T; t += 2 * stride) {
        const int t2 = t + stride;
        const bool has2 = (t2 < T);

        const int row1 = sent[t];
        const int row2 = has2 ? sent[t2] : row1;
        const float4* e1 = (const float4*)(emb + (size_t)row1 * 1024);
        const float4* e2 = (const float4*)(emb + (size_t)row2 * 1024);

        float acc1 = 0.0f, acc2 = 0.0f;
#pragma unroll
        for (int i = 0; i < 8; i++) {
            float4 a = __ldg(&e1[lane + 32 * i]);
            float4 b = __ldg(&e2[lane + 32 * i]);
            acc1 = fmaf(a.x, wr[i].x, acc1);
            acc1 = fmaf(a.y, wr[i].y, acc1);
            acc1 = fmaf(a.z, wr[i].z, acc1);
            acc1 = fmaf(a.w, wr[i].w, acc1);
            acc2 = fmaf(b.x, wr[i].x, acc2);
            acc2 = fmaf(b.y, wr[i].y, acc2);
            acc2 = fmaf(b.z, wr[i].z, acc2);
            acc2 = fmaf(b.w, wr[i].w, acc2);
        }
#pragma unroll
        for (int s = 16; s > 0; s >>= 1) {
            acc1 += __shfl_xor_sync(0xffffffffu, acc1, s);
            acc2 += __shfl_xor_sync(0xffffffffu, acc2, s);
        }
        if (lane == 0) {
            xrow[t] = acc1 + bias;
            if (has2) xrow[t2] = acc2 + bias;
        }
    }
}

// ---------------------------------------------------------------------------
// LSTM step: 16-lane group, lane ll = g*4 + w; shuffles use width=16.
// qlayer(a)[w]: w=0: c1c2c3  w=1: c0c1  w=2: c0c1c2  w=3: c0c1c2c3
// ---------------------------------------------------------------------------
struct K2Consts {
    float wr0, wr1, wr2, wr3;
    int hs1, hs2, hs3;
    int sA, sB, sC;
    bool wz0, wB1, wC12;
    float act_s, act_a, act_b;
    int w;
};

__device__ __forceinline__ void lstm_step(float x, float& h, float& c,
                                          const K2Consts& K)
{
    const unsigned FULL = 0xffffffffu;

    const float h1 = __shfl_sync(FULL, h, K.hs1, 16);
    const float h2 = __shfl_sync(FULL, h, K.hs2, 16);
    const float h3 = __shfl_sync(FULL, h, K.hs3, 16);

    const float pa = fmaf(h, K.wr0, x);
    const float pb = h1 * K.wr1;
    const float pc = fmaf(h2, K.wr2, pb);
    const float pd = fmaf(h3, K.wr3, pa);
    const float pre = pc + pd;

    const float cs = __cosf(pre);

    const float fA  = __shfl_sync(FULL, cs, K.sA, 16);
    const float fBs = __shfl_sync(FULL, cs, K.sB, 16);
    const float fCs = __shfl_sync(FULL, cs, K.sC, 16);
    const float f0 = K.wz0  ? 1.0f : cs;
    const float fB = K.wB1  ? 1.0f : fBs;
    const float fC = K.wC12 ? 1.0f : fCs;
    const float z  = (f0 * fA) * (fB * fC);

    const float gv = fmaf(tanh_rat(K.act_s * z), K.act_a, K.act_b);

    const float fv = __shfl_sync(FULL, gv, 0 + K.w, 16);
    const float iv = __shfl_sync(FULL, gv, 4 + K.w, 16);
    const float uv = __shfl_sync(FULL, gv, 8 + K.w, 16);
    const float ov = __shfl_sync(FULL, gv, 12 + K.w, 16);

    c = fmaf(fv, c, iv * uv);
    h = ov * tanh_rat(c);
}

__device__ __forceinline__ void k2_make_consts(K2Consts& K,
    const float* Wf, const float* Wi, const float* Wu, const float* Wo, int ll)
{
    const int g = ll >> 2, w = ll & 3;
    const int base = ll & ~3;
    const float* Wg = (g == 0) ? Wf : (g == 1) ? Wi : (g == 2) ? Wu : Wo;
    K.wr0 = Wg[w * 1028 + 1024 + w];
    K.wr1 = Wg[w * 1028 + 1024 + ((w + 1) & 3)];
    K.wr2 = Wg[w * 1028 + 1024 + ((w + 2) & 3)];
    K.wr3 = Wg[w * 1028 + 1024 + ((w + 3) & 3)];
    K.hs1 = base + ((w + 1) & 3);
    K.hs2 = base + ((w + 2) & 3);
    K.hs3 = base + ((w + 3) & 3);
    K.sA = base + ((w == 0) ? 1 : 0);
    K.sB = base + ((w >= 2) ? 1 : ((w == 0) ? 2 : 0));
    K.sC = base + ((w == 0) ? 3 : ((w == 3) ? 2 : 0));
    K.wz0  = (w == 0);
    K.wB1  = (w == 1);
    K.wC12 = (w == 1) || (w == 2);
    K.act_s = (g == 2) ? 1.0f : 0.5f;
    K.act_a = (g == 2) ? 1.0f : 0.5f;
    K.act_b = (g == 2) ? 0.0f : 0.5f;
    K.w = w;
}

// ---------------------------------------------------------------------------
// K2 sweep: each 16-lane group owns time-block b = gid, runs KS serial steps
// from the previous sweep's boundary state (Jacobi iteration). sweep==0
// forces zero boundaries so every graph replay is deterministic.
// ---------------------------------------------------------------------------
__global__ void k2_sweep(const float* __restrict__ Wf, const float* __restrict__ Wi,
                         const float* __restrict__ Wu, const float* __restrict__ Wo,
                         int T, int sweep, int rd, int wr, int writeH)
{
    const int gid = (int)((blockIdx.x * blockDim.x + threadIdx.x) >> 4);  // time-block b
    const int ll  = threadIdx.x & 15;
    const int w   = ll & 3;

    K2Consts K;
    k2_make_consts(K, Wf, Wi, Wu, Wo, ll);

    const int t0 = gid * KS;

    // preload all KS x-values for this block into registers
    float4 xv[KS / 4];
    const float* xrow = &g_XpreT[ll * T_PAD + t0];
#pragma unroll
    for (int q = 0; q < KS / 4; q++)
        xv[q] = *(const float4*)&xrow[4 * q];

    float h = 0.0f, c = 0.0f;
    if (sweep != 0 && gid != 0) {
        h = g_Bh[rd][gid - 1][w];
        c = g_Bc[rd][gid - 1][w];
    }

    const bool doH = (writeH != 0) && (ll < 4) && (t0 < T);
    float* hrow = &g_houtT[w * T_PAD + t0];

#pragma unroll 2
    for (int q = 0; q < KS / 4; q++) {
        lstm_step(xv[q].x, h, c, K); const float hA = h;
        lstm_step(xv[q].y, h, c, K); const float hB = h;
        lstm_step(xv[q].z, h, c, K); const float hC = h;
        lstm_step(xv[q].w, h, c, K); const float hD = h;
        if (doH)
            *(float4*)&hrow[4 * q] = make_float4(hA, hB, hC, hD);
    }

    if (ll < 4) {
        g_Bh[wr][gid][w] = h;
        g_Bc[wr][gid][w] = c;
    }
}

// ---------------------------------------------------------------------------
// K3: tag logits + log_softmax. One warp per timestep; lane covers two tags.
// ---------------------------------------------------------------------------
__global__ void k3_tag(const float* __restrict__ Wt, const float* __restrict__ bt,
                       float* __restrict__ out, int T, int TAG)
{
    const int warp_global = (int)((blockIdx.x * blockDim.x + threadIdx.x) >> 5);
    const int lane = threadIdx.x & 31;
    if (warp_global >= T) return;
    const int t = warp_global;

    const float h0 = g_houtT[0 * T_PAD + t];
    const float h1 = g_houtT[1 * T_PAD + t];
    const float h2 = g_houtT[2 * T_PAD + t];
    const float h3 = g_houtT[3 * T_PAD + t];

    const int tag0 = lane;
    const int tag1 = lane + 32;

    float l0 = -1e30f, l1 = -1e30f;
    if (tag0 < TAG) {
        const float* wr = Wt + tag0 * 4;
        l0 = bt[tag0] + h0 * wr[0] + h1 * wr[1] + h2 * wr[2] + h3 * wr[3];
    }
    if (tag1 < TAG) {
        const float* wr = Wt + tag1 * 4;
        l1 = bt[tag1] + h0 * wr[0] + h1 * wr[1] + h2 * wr[2] + h3 * wr[3];
    }

    float m = fmaxf(l0, l1);
#pragma unroll
    for (int s = 16; s > 0; s >>= 1)
        m = fmaxf(m, __shfl_xor_sync(0xffffffffu, m, s));

    float s0 = (tag0 < TAG) ? __expf(l0 - m) : 0.0f;
    float s1 = (tag1 < TAG) ? __expf(l1 - m) : 0.0f;
    float ssum = s0 + s1;
#pragma unroll
    for (int s = 16; s > 0; s >>= 1)
        ssum += __shfl_xor_sync(0xffffffffu, ssum, s);

    const float lse = m + __logf(ssum);
    if (tag0 < TAG) out[t * TAG + tag0] = l0 - lse;
    if (tag1 < TAG) out[t * TAG + tag1] = l1 - lse;
}

// ---------------------------------------------------------------------------
extern "C" void kernel_launch(void* const* d_in, const int* in_sizes, int n_in,
                              void* d_out, int out_size)
{
    const int*   sent = (const int*)  d_in[0];
    const float* emb  = (const float*)d_in[1];
    const float* Wf   = (const float*)d_in[2];
    const float* bf   = (const float*)d_in[3];
    const float* Wi   = (const float*)d_in[4];
    const float* bi   = (const float*)d_in[5];
    const float* Wu   = (const float*)d_in[6];
    const float* bu   = (const float*)d_in[7];
    const float* Wo   = (const float*)d_in[8];
    const float* bo   = (const float*)d_in[9];
    const float* thf  = (const float*)d_in[10];
    const float* thi  = (const float*)d_in[11];
    const float* thu  = (const float*)d_in[12];
    const float* tho  = (const float*)d_in[13];
    const float* Wt   = (const float*)d_in[14];
    const float* bt   = (const float*)d_in[15];

    int T = in_sizes[0];
    if (T > T_MAX) T = T_MAX;
    const int TAG = in_sizes[14] / 4;   // Wt is [TAG, 4]

    k1_pre<<<1024, 512>>>(sent, emb, Wf, bf, Wi, bi, Wu, bu, Wo, bo,
                          thf, thi, thu, tho, T);

    // Jacobi sweeps over block boundaries: NB groups of 16 lanes, 128 thr/CTA
    const int sweep_blocks = NB / 8;   // 8 groups per 128-thread CTA
    for (int s = 0; s < NSWEEP; s++) {
        k2_sweep<<<sweep_blocks, 128>>>(Wf, Wi, Wu, Wo, T,
                                        s, s & 1, (s + 1) & 1, 0);
    }
    // output sweep reads the last-written buffer (NSWEEP & 1)
    k2_sweep<<<sweep_blocks, 128>>>(Wf, Wi, Wu, Wo, T,
                                    NSWEEP, NSWEEP & 1, (NSWEEP + 1) & 1, 1);

    const int warps_per_block = 8;
    const int blocks = (T + warps_per_block - 1) / warps_per_block;
    k3_tag<<<blocks, warps_per_block * 32>>>(Wt, bt, (float*)d_out, T, TAG);
}